// round 3
// baseline (speedup 1.0000x reference)
#include <cuda_runtime.h>
#include <math.h>
#include <stdint.h>

#define T 2048
#define H 1024
#define NH 16
#define NKV 4
#define HD 64
#define NE 32
#define TOPK 4
#define NG 4
#define IM 384
#define ISH 384
#define QKV_N 1536   // (NH + 2*NKV) * HD
#define V_OFF 1280   // (NH + NKV) * HD
#define K_OFF 1024   // NH * HD
#define EPS 1e-5f
#define NPAIRS (T*TOPK)   // 8192

// ---------------- scratch (static device globals; no runtime alloc) ----------------
// Reused regions (disjoint lifetimes):
//   g_x1: hidden1 (pre-attn)        -> sout  (shared-expert output)
//   g_x3: attno   (attn output)     -> sgu   (shared-expert up, 1.57M <= 2M)
//   g_x4: hidden2 (Wo output)       -> sact  (shared-expert act, 0.79M <= 2M)
static __device__ float g_x1[T*H];          // hidden1 / sout
static __device__ float g_x3[T*H];          // attno  / sgu
static __device__ float g_x4[T*H];          // hidden2 / sact
static __device__ float g_resid1[T*H];
static __device__ float g_qkv[T*QKV_N];
static __device__ float g_resid2[T*H];
static __device__ float g_hidden3[T*H];
static __device__ int   g_ids[NPAIRS];
static __device__ float g_wts[NPAIRS];
static __device__ int   g_cnt[NE];
static __device__ int   g_off[NE];
static __device__ int   g_fill[NE];
static __device__ int   g_tok[NPAIRS];      // position -> token
static __device__ int   g_pos[NPAIRS];      // (token,slot) -> position
static __device__ float g_gu[(size_t)NPAIRS*2*IM];
static __device__ float g_act[(size_t)NPAIRS*IM];
static __device__ float g_down[(size_t)NPAIRS*H];

#define g_hidden1 g_x1
#define g_sout    g_x1
#define g_attno   g_x3
#define g_sgu     g_x3
#define g_hidden2 g_x4
#define g_sact    g_x4

// ---------------- add + RMSNorm ----------------
// mode 0: resid1 = ext_h + ext_r; hidden1 = rms(resid1)*w
// mode 1: resid2 = g_hidden2 + g_resid1; hidden3 = rms(resid2)*w
__global__ void add_rms_kernel(const float* __restrict__ ext_h,
                               const float* __restrict__ ext_r,
                               const float* __restrict__ w, int mode) {
    int t = blockIdx.x, tid = threadIdx.x;
    const float* hp; const float* rp; float* rout; float* nout;
    if (mode == 0) { hp = ext_h + (size_t)t*H; rp = ext_r + (size_t)t*H;
                     rout = g_resid1 + (size_t)t*H; nout = g_hidden1 + (size_t)t*H; }
    else           { hp = g_hidden2 + (size_t)t*H; rp = g_resid1 + (size_t)t*H;
                     rout = g_resid2 + (size_t)t*H; nout = g_hidden3 + (size_t)t*H; }
    float v[4]; float ss = 0.f;
    #pragma unroll
    for (int i = 0; i < 4; i++) {
        int idx = tid + i*256;
        v[i] = hp[idx] + rp[idx];
        rout[idx] = v[i];
        ss += v[i]*v[i];
    }
    __shared__ float red[256];
    red[tid] = ss; __syncthreads();
    for (int s = 128; s > 0; s >>= 1) { if (tid < s) red[tid] += red[tid+s]; __syncthreads(); }
    float scale = rsqrtf(red[0] * (1.0f/H) + EPS);
    #pragma unroll
    for (int i = 0; i < 4; i++) {
        int idx = tid + i*256;
        nout[idx] = v[i]*scale*w[idx];
    }
}

// ---------------- generic tiled SGEMM body: C[M,N] = A[M,K] @ B[K,N] ----------------
// 64x64 tile, BK=16, 256 threads, 4x4 microtile. M multiple of 64 (grid.y covers M).
__device__ __forceinline__ void sgemm_body(const float* __restrict__ A,
                                           const float* __restrict__ B,
                                           float* __restrict__ C, int N, int K) {
    __shared__ float As[16][64];
    __shared__ float Bs[16][64];
    int m0 = blockIdx.y * 64;
    int n0 = blockIdx.x * 64;
    int tid = threadIdx.x;
    int tx = tid & 15, ty = tid >> 4;
    float acc[4][4] = {};
    for (int k0 = 0; k0 < K; k0 += 16) {
        #pragma unroll
        for (int i = 0; i < 4; i++) {
            int e = i*256 + tid; int m = e >> 4, k = e & 15;
            As[k][m] = A[(size_t)(m0+m)*K + k0 + k];
        }
        #pragma unroll
        for (int i = 0; i < 4; i++) {
            int e = i*256 + tid; int n = e & 63, k = e >> 6;
            Bs[k][n] = B[(size_t)(k0+k)*N + n0 + n];
        }
        __syncthreads();
        #pragma unroll
        for (int k = 0; k < 16; k++) {
            float a[4], b[4];
            #pragma unroll
            for (int i = 0; i < 4; i++) a[i] = As[k][ty*4+i];
            #pragma unroll
            for (int j = 0; j < 4; j++) b[j] = Bs[k][tx*4+j];
            #pragma unroll
            for (int i = 0; i < 4; i++)
                #pragma unroll
                for (int j = 0; j < 4; j++) acc[i][j] += a[i]*b[j];
        }
        __syncthreads();
    }
    #pragma unroll
    for (int i = 0; i < 4; i++)
        #pragma unroll
        for (int j = 0; j < 4; j++)
            C[(size_t)(m0+ty*4+i)*N + n0+tx*4+j] = acc[i][j];
}

__global__ void k_gemm_qkv(const float* __restrict__ Wqkv)  { sgemm_body(g_hidden1, Wqkv,   g_qkv,   QKV_N, H); }
__global__ void k_gemm_wo(const float* __restrict__ Wo)     { sgemm_body(g_attno,   Wo,     g_hidden2, H,   H); }
__global__ void k_gemm_sgu(const float* __restrict__ W)     { sgemm_body(g_hidden3, W,      g_sgu,  2*ISH, H); }
__global__ void k_gemm_sdown(const float* __restrict__ W)   { sgemm_body(g_sact,    W,      g_sout,  H,  ISH); }

// ---------------- Q/K rmsnorm + partial RoPE (in-place on g_qkv) ----------------
__global__ void qk_norm_rope_kernel(const float* __restrict__ qw,
                                    const float* __restrict__ kw,
                                    const int* __restrict__ pos) {
    int t = blockIdx.x, head = blockIdx.y, d = threadIdx.x;  // 64 threads
    float* base; const float* w;
    if (head < NH) { base = g_qkv + (size_t)t*QKV_N + head*HD; w = qw; }
    else           { base = g_qkv + (size_t)t*QKV_N + K_OFF + (head-NH)*HD; w = kw; }
    float x = base[d];
    __shared__ float red[64];
    red[d] = x*x; __syncthreads();
    for (int s = 32; s > 0; s >>= 1) { if (d < s) red[d] += red[d+s]; __syncthreads(); }
    float scale = rsqrtf(red[0] * (1.0f/HD) + EPS);
    float y = x * scale * w[d];
    __shared__ float sy[64];
    sy[d] = y; __syncthreads();
    if (d < 16) {
        float p = (float)pos[t];
        float inv = powf(10000.0f, -(float)d / 16.0f);
        float ang = p * inv;
        float c = cosf(ang), s = sinf(ang);
        float x1 = sy[d], x2 = sy[d+16];
        base[d]    = x1*c - x2*s;
        base[d+16] = x1*s + x2*c;
    } else if (d >= 32) {
        base[d] = y;
    }
}

// ---------------- attention: one block per (query t, head h) ----------------
__global__ void attn_kernel() {
    int t = blockIdx.x, h = blockIdx.y, tid = threadIdx.x;  // 256 threads
    int kh = h >> 2;
    __shared__ float sq[64];
    __shared__ float sc[T];
    __shared__ float red[256];
    const float* qp = g_qkv + (size_t)t*QKV_N + h*HD;
    if (tid < 64) sq[tid] = qp[tid];
    __syncthreads();
    int L = t + 1;
    float lmax = -1e30f;
    for (int s = tid; s < L; s += 256) {
        const float4* kp = (const float4*)(g_qkv + (size_t)s*QKV_N + K_OFF + kh*HD);
        float acc = 0.f;
        #pragma unroll
        for (int d4 = 0; d4 < 16; d4++) {
            float4 kv = kp[d4];
            acc += sq[d4*4+0]*kv.x + sq[d4*4+1]*kv.y + sq[d4*4+2]*kv.z + sq[d4*4+3]*kv.w;
        }
        acc *= 0.125f;  // HD^-0.5
        sc[s] = acc;
        lmax = fmaxf(lmax, acc);
    }
    red[tid] = lmax; __syncthreads();
    for (int s2 = 128; s2 > 0; s2 >>= 1) { if (tid < s2) red[tid] = fmaxf(red[tid], red[tid+s2]); __syncthreads(); }
    float m = red[0];
    __syncthreads();
    float lsum = 0.f;
    for (int s = tid; s < L; s += 256) { float e = __expf(sc[s] - m); sc[s] = e; lsum += e; }
    red[tid] = lsum; __syncthreads();
    for (int s2 = 128; s2 > 0; s2 >>= 1) { if (tid < s2) red[tid] += red[tid+s2]; __syncthreads(); }
    float inv = 1.0f / red[0];
    __syncthreads();
    int d = tid & 63, c = tid >> 6;
    float acc = 0.f;
    for (int s = c; s < L; s += 4)
        acc += sc[s] * g_qkv[(size_t)s*QKV_N + V_OFF + kh*HD + d];
    red[tid] = acc; __syncthreads();
    if (c == 0)
        g_attno[(size_t)t*H + h*HD + d] = (red[d] + red[d+64] + red[d+128] + red[d+192]) * inv;
}

// ---------------- router ----------------
__global__ void router_kernel(const float* __restrict__ Wg,
                              const float* __restrict__ gbias) {
    int t = blockIdx.x, tid = threadIdx.x;  // 32 threads
    __shared__ float sh[H];
    #pragma unroll
    for (int i = 0; i < H/32; i++) sh[tid + 32*i] = g_hidden3[(size_t)t*H + tid + 32*i];
    __syncthreads();
    float acc = 0.f;
    for (int k = 0; k < H; k++) acc += sh[k] * Wg[k*NE + tid];
    float scr = 1.0f / (1.0f + expf(-acc));
    float sfc = scr + gbias[tid];
    __shared__ float s_scr[NE], s_sfc[NE];
    s_scr[tid] = scr; s_sfc[tid] = sfc;
    __syncthreads();
    if (tid == 0) {
        float gs[NG];
        for (int g = 0; g < NG; g++) {
            float m1 = -1e30f, m2 = -1e30f;
            for (int j = 0; j < NE/NG; j++) {
                float v = s_sfc[g*(NE/NG) + j];
                if (v > m1) { m2 = m1; m1 = v; } else if (v > m2) m2 = v;
            }
            gs[g] = m1 + m2;
        }
        int g1 = 0; for (int g = 1; g < NG; g++) if (gs[g] > gs[g1]) g1 = g;
        int g2 = -1; for (int g = 0; g < NG; g++) { if (g == g1) continue; if (g2 < 0 || gs[g] > gs[g2]) g2 = g; }
        bool taken[NE];
        for (int e = 0; e < NE; e++) taken[e] = false;
        int ids[TOPK]; float wsum = 0.f;
        for (int j = 0; j < TOPK; j++) {
            int best = -1;
            for (int e = 0; e < NE; e++) {
                int g = e >> 3;
                if (g != g1 && g != g2) continue;
                if (taken[e]) continue;
                if (best < 0 || s_sfc[e] > s_sfc[best]) best = e;
            }
            taken[best] = true; ids[j] = best; wsum += s_scr[best];
        }
        for (int j = 0; j < TOPK; j++) {
            g_ids[t*TOPK + j] = ids[j];
            g_wts[t*TOPK + j] = s_scr[ids[j]] / wsum;
            atomicAdd(&g_cnt[ids[j]], 1);
        }
    }
}

__global__ void reset_kernel() { if (threadIdx.x < NE) g_cnt[threadIdx.x] = 0; }

__global__ void scan_kernel() {
    int tid = threadIdx.x;
    if (tid < NE) g_fill[tid] = 0;
    if (tid == 0) {
        int a = 0;
        for (int e = 0; e < NE; e++) { g_off[e] = a; a += g_cnt[e]; }
    }
}

__global__ void place_kernel() {
    int idx = blockIdx.x*blockDim.x + threadIdx.x;
    if (idx >= NPAIRS) return;
    int e = g_ids[idx];
    int p = g_off[e] + atomicAdd(&g_fill[e], 1);
    g_tok[p] = idx >> 2;
    g_pos[idx] = p;
}

// ---------------- expert up GEMM (gathered A rows) ----------------
__global__ void gemm_moe_up(const float* __restrict__ Wgu) {
    int e = blockIdx.z;
    int Me = g_cnt[e];
    int m0 = blockIdx.x * 64;
    if (m0 >= Me) return;
    int off = g_off[e];
    int n0 = blockIdx.y * 64;
    const float* B = Wgu + (size_t)e * H * (2*IM);
    __shared__ float As[16][64];
    __shared__ float Bs[16][64];
    __shared__ int srow[64];
    int tid = threadIdx.x;
    if (tid < 64) { int r = m0 + tid; srow[tid] = (r < Me) ? g_tok[off + r] : -1; }
    __syncthreads();
    int tx = tid & 15, ty = tid >> 4;
    float acc[4][4] = {};
    for (int k0 = 0; k0 < H; k0 += 16) {
        #pragma unroll
        for (int i = 0; i < 4; i++) {
            int el = i*256 + tid; int m = el >> 4, k = el & 15;
            int row = srow[m];
            As[k][m] = (row >= 0) ? g_hidden3[(size_t)row*H + k0 + k] : 0.f;
        }
        #pragma unroll
        for (int i = 0; i < 4; i++) {
            int el = i*256 + tid; int n = el & 63, k = el >> 6;
            Bs[k][n] = B[(size_t)(k0+k)*(2*IM) + n0 + n];
        }
        __syncthreads();
        #pragma unroll
        for (int k = 0; k < 16; k++) {
            float a[4], b[4];
            #pragma unroll
            for (int i = 0; i < 4; i++) a[i] = As[k][ty*4+i];
            #pragma unroll
            for (int j = 0; j < 4; j++) b[j] = Bs[k][tx*4+j];
            #pragma unroll
            for (int i = 0; i < 4; i++)
                #pragma unroll
                for (int j = 0; j < 4; j++) acc[i][j] += a[i]*b[j];
        }
        __syncthreads();
    }
    #pragma unroll
    for (int i = 0; i < 4; i++) {
        int r = m0 + ty*4 + i;
        if (r < Me)
            #pragma unroll
            for (int j = 0; j < 4; j++)
                g_gu[(size_t)(off+r)*(2*IM) + n0 + tx*4 + j] = acc[i][j];
    }
}

// ---------------- expert down GEMM (contiguous A rows per expert) ----------------
__global__ void gemm_moe_down(const float* __restrict__ Wd) {
    int e = blockIdx.z;
    int Me = g_cnt[e];
    int m0 = blockIdx.x * 64;
    if (m0 >= Me) return;
    int off = g_off[e];
    int n0 = blockIdx.y * 64;
    const float* A = g_act + (size_t)off * IM;
    const float* B = Wd + (size_t)e * IM * H;
    __shared__ float As[16][64];
    __shared__ float Bs[16][64];
    int tid = threadIdx.x;
    int tx = tid & 15, ty = tid >> 4;
    float acc[4][4] = {};
    for (int k0 = 0; k0 < IM; k0 += 16) {
        #pragma unroll
        for (int i = 0; i < 4; i++) {
            int el = i*256 + tid; int m = el >> 4, k = el & 15;
            As[k][m] = (m0 + m < Me) ? A[(size_t)(m0+m)*IM + k0 + k] : 0.f;
        }
        #pragma unroll
        for (int i = 0; i < 4; i++) {
            int el = i*256 + tid; int n = el & 63, k = el >> 6;
            Bs[k][n] = B[(size_t)(k0+k)*H + n0 + n];
        }
        __syncthreads();
        #pragma unroll
        for (int k = 0; k < 16; k++) {
            float a[4], b[4];
            #pragma unroll
            for (int i = 0; i < 4; i++) a[i] = As[k][ty*4+i];
            #pragma unroll
            for (int j = 0; j < 4; j++) b[j] = Bs[k][tx*4+j];
            #pragma unroll
            for (int i = 0; i < 4; i++)
                #pragma unroll
                for (int j = 0; j < 4; j++) acc[i][j] += a[i]*b[j];
        }
        __syncthreads();
    }
    #pragma unroll
    for (int i = 0; i < 4; i++) {
        int r = m0 + ty*4 + i;
        if (r < Me)
            #pragma unroll
            for (int j = 0; j < 4; j++)
                g_down[(size_t)(off+r)*H + n0 + tx*4 + j] = acc[i][j];
    }
}

// ---------------- SwiGLU activation ----------------
__global__ void act_kernel(int mode) {
    int idx = blockIdx.x*blockDim.x + threadIdx.x;
    if (mode == 0) {
        if (idx >= NPAIRS*IM) return;
        int r = idx / IM, j = idx % IM;
        float a = g_gu[(size_t)r*2*IM + j];
        float b = g_gu[(size_t)r*2*IM + IM + j];
        g_act[idx] = a / (1.0f + expf(-a)) * b;
    } else {
        if (idx >= T*ISH) return;
        int r = idx / ISH, j = idx % ISH;
        float a = g_sgu[(size_t)r*2*ISH + j];
        float b = g_sgu[(size_t)r*2*ISH + ISH + j];
        g_sact[idx] = a / (1.0f + expf(-a)) * b;
    }
}

// ---------------- final combine: out = routed*RSF + shared; out2 = resid2 ----------------
__global__ void combine_kernel(float* __restrict__ out, int write_resid) {
    int idx = blockIdx.x*blockDim.x + threadIdx.x;
    if (idx >= T*H) return;
    int t = idx >> 10;
    int hh = idx & 1023;
    float acc = 0.f;
    #pragma unroll
    for (int s = 0; s < TOPK; s++) {
        int p = g_pos[t*TOPK + s];
        acc += g_wts[t*TOPK + s] * g_down[(size_t)p*H + hh];
    }
    out[idx] = acc + g_sout[idx];  // RSF = 1.0
    if (write_resid) out[(size_t)T*H + idx] = g_resid2[idx];
}

// ---------------- launch ----------------
extern "C" void kernel_launch(void* const* d_in, const int* in_sizes, int n_in,
                              void* d_out, int out_size) {
    const float* hidden_states = (const float*)d_in[0];
    const float* residual      = (const float*)d_in[1];
    const float* in_ln_w       = (const float*)d_in[2];
    const float* post_ln_w     = (const float*)d_in[3];
    const float* q_norm_w      = (const float*)d_in[4];
    const float* k_norm_w      = (const float*)d_in[5];
    const float* Wqkv          = (const float*)d_in[6];
    const float* Wo            = (const float*)d_in[7];
    const float* Wg            = (const float*)d_in[8];
    const float* gate_bias     = (const float*)d_in[9];
    const float* Wgu           = (const float*)d_in[10];
    const float* Wd            = (const float*)d_in[11];
    const float* Wgu_sh        = (const float*)d_in[12];
    const float* Wd_sh         = (const float*)d_in[13];
    const int*   positions     = (const int*)d_in[14];
    float* out = (float*)d_out;

    reset_kernel<<<1, 32>>>();
    add_rms_kernel<<<T, 256>>>(hidden_states, residual, in_ln_w, 0);
    k_gemm_qkv<<<dim3(QKV_N/64, T/64), 256>>>(Wqkv);
    qk_norm_rope_kernel<<<dim3(T, NH + NKV), 64>>>(q_norm_w, k_norm_w, positions);
    attn_kernel<<<dim3(T, NH), 256>>>();
    k_gemm_wo<<<dim3(H/64, T/64), 256>>>(Wo);
    add_rms_kernel<<<T, 256>>>(nullptr, nullptr, post_ln_w, 1);
    router_kernel<<<T, 32>>>(Wg, gate_bias);
    scan_kernel<<<1, 32>>>();
    place_kernel<<<(NPAIRS + 255)/256, 256>>>();
    gemm_moe_up<<<dim3(T/64, 2*IM/64, NE), 256>>>(Wgu);
    act_kernel<<<(NPAIRS*IM + 255)/256, 256>>>(0);
    gemm_moe_down<<<dim3(T/64, H/64, NE), 256>>>(Wd);
    k_gemm_sgu<<<dim3(2*ISH/64, T/64), 256>>>(Wgu_sh);
    act_kernel<<<(T*ISH + 255)/256, 256>>>(1);
    k_gemm_sdown<<<dim3(H/64, T/64), 256>>>(Wd_sh);
    combine_kernel<<<(T*H + 255)/256, 256>>>(out, (out_size >= 2*T*H) ? 1 : 0);
}

// round 4
// speedup vs baseline: 2.5167x; 2.5167x over previous
#include <cuda_runtime.h>
#include <math.h>
#include <stdint.h>

#define T 2048
#define H 1024
#define NH 16
#define NKV 4
#define HD 64
#define NE 32
#define TOPK 4
#define NG 4
#define IM 384
#define ISH 384
#define QKV_N 1536   // (NH + 2*NKV) * HD
#define V_OFF 1280   // (NH + NKV) * HD
#define K_OFF 1024   // NH * HD
#define EPS 1e-5f
#define NPAIRS (T*TOPK)   // 8192

// ---------------- scratch (static device globals; no runtime alloc) ----------------
static __device__ float g_x1[T*H];          // hidden1 / sout
static __device__ float g_x3[T*H];          // attno  / sgu
static __device__ float g_x4[T*H];          // hidden2 / sact
static __device__ float g_resid1[T*H];
static __device__ float g_qkv[T*QKV_N];
static __device__ float g_resid2[T*H];
static __device__ float g_hidden3[T*H];
static __device__ int   g_ids[NPAIRS];
static __device__ float g_wts[NPAIRS];
static __device__ int   g_cnt[NE];
static __device__ int   g_off[NE];
static __device__ int   g_fill[NE];
static __device__ int   g_tok[NPAIRS];
static __device__ int   g_pos[NPAIRS];
static __device__ float g_gu[(size_t)NPAIRS*2*IM];
static __device__ float g_act[(size_t)NPAIRS*IM];
static __device__ float g_down[(size_t)NPAIRS*H];

#define g_hidden1 g_x1
#define g_sout    g_x1
#define g_attno   g_x3
#define g_sgu     g_x3
#define g_hidden2 g_x4
#define g_sact    g_x4

// ---------------- add + RMSNorm ----------------
__global__ void add_rms_kernel(const float* __restrict__ ext_h,
                               const float* __restrict__ ext_r,
                               const float* __restrict__ w, int mode) {
    int t = blockIdx.x, tid = threadIdx.x;
    const float* hp; const float* rp; float* rout; float* nout;
    if (mode == 0) { hp = ext_h + (size_t)t*H; rp = ext_r + (size_t)t*H;
                     rout = g_resid1 + (size_t)t*H; nout = g_hidden1 + (size_t)t*H; }
    else           { hp = g_hidden2 + (size_t)t*H; rp = g_resid1 + (size_t)t*H;
                     rout = g_resid2 + (size_t)t*H; nout = g_hidden3 + (size_t)t*H; }
    float v[4]; float ss = 0.f;
    #pragma unroll
    for (int i = 0; i < 4; i++) {
        int idx = tid + i*256;
        v[i] = hp[idx] + rp[idx];
        rout[idx] = v[i];
        ss += v[i]*v[i];
    }
    __shared__ float red[256];
    red[tid] = ss; __syncthreads();
    for (int s = 128; s > 0; s >>= 1) { if (tid < s) red[tid] += red[tid+s]; __syncthreads(); }
    float scale = rsqrtf(red[0] * (1.0f/H) + EPS);
    #pragma unroll
    for (int i = 0; i < 4; i++) {
        int idx = tid + i*256;
        nout[idx] = v[i]*scale*w[idx];
    }
}

// ======== SGEMM 128x128x16, 256 threads, 8x8 microtile ========
// C[M,N] = A[M,K] @ B[K,N]; M,N multiples of 128 (grid covers), K multiple of 16.
__device__ __forceinline__ void sgemm128(const float* __restrict__ A,
                                         const float* __restrict__ B,
                                         float* __restrict__ C, int N, int K) {
    __shared__ float As[16][132];
    __shared__ float Bs[16][128];
    int m0 = blockIdx.y * 128;
    int n0 = blockIdx.x * 128;
    int tid = threadIdx.x;
    int tx = tid & 15, ty = tid >> 4;
    float acc[8][8] = {};
    for (int k0 = 0; k0 < K; k0 += 16) {
        #pragma unroll
        for (int i = 0; i < 2; i++) {
            int idx = tid + i*256;            // 0..511
            int m = idx >> 2, kq = (idx & 3) << 2;
            float4 v = *(const float4*)&A[(size_t)(m0+m)*K + k0 + kq];
            As[kq+0][m] = v.x; As[kq+1][m] = v.y; As[kq+2][m] = v.z; As[kq+3][m] = v.w;
        }
        #pragma unroll
        for (int i = 0; i < 2; i++) {
            int idx = tid + i*256;
            int k = idx >> 5, n = (idx & 31) << 2;
            *(float4*)&Bs[k][n] = *(const float4*)&B[(size_t)(k0+k)*N + n0 + n];
        }
        __syncthreads();
        #pragma unroll
        for (int k = 0; k < 16; k++) {
            float a[8], b[8];
            *(float4*)&a[0] = *(float4*)&As[k][ty*8];
            *(float4*)&a[4] = *(float4*)&As[k][ty*8+4];
            *(float4*)&b[0] = *(float4*)&Bs[k][tx*8];
            *(float4*)&b[4] = *(float4*)&Bs[k][tx*8+4];
            #pragma unroll
            for (int i = 0; i < 8; i++)
                #pragma unroll
                for (int j = 0; j < 8; j++) acc[i][j] += a[i]*b[j];
        }
        __syncthreads();
    }
    #pragma unroll
    for (int i = 0; i < 8; i++) {
        float* cp = &C[(size_t)(m0+ty*8+i)*N + n0+tx*8];
        *(float4*)&cp[0] = make_float4(acc[i][0], acc[i][1], acc[i][2], acc[i][3]);
        *(float4*)&cp[4] = make_float4(acc[i][4], acc[i][5], acc[i][6], acc[i][7]);
    }
}

__global__ void __launch_bounds__(256) k_gemm_qkv(const float* __restrict__ W)   { sgemm128(g_hidden1, W, g_qkv,    QKV_N, H); }
__global__ void __launch_bounds__(256) k_gemm_wo(const float* __restrict__ W)    { sgemm128(g_attno,   W, g_hidden2, H,    H); }
__global__ void __launch_bounds__(256) k_gemm_sgu(const float* __restrict__ W)   { sgemm128(g_hidden3, W, g_sgu,    2*ISH, H); }
__global__ void __launch_bounds__(256) k_gemm_sdown(const float* __restrict__ W) { sgemm128(g_sact,    W, g_sout,   H,   ISH); }

// ---------------- Q/K rmsnorm + partial RoPE (in-place on g_qkv) ----------------
__global__ void qk_norm_rope_kernel(const float* __restrict__ qw,
                                    const float* __restrict__ kw,
                                    const int* __restrict__ pos) {
    int t = blockIdx.x, head = blockIdx.y, d = threadIdx.x;  // 64 threads
    float* base; const float* w;
    if (head < NH) { base = g_qkv + (size_t)t*QKV_N + head*HD; w = qw; }
    else           { base = g_qkv + (size_t)t*QKV_N + K_OFF + (head-NH)*HD; w = kw; }
    float x = base[d];
    __shared__ float red[64];
    red[d] = x*x; __syncthreads();
    for (int s = 32; s > 0; s >>= 1) { if (d < s) red[d] += red[d+s]; __syncthreads(); }
    float scale = rsqrtf(red[0] * (1.0f/HD) + EPS);
    float y = x * scale * w[d];
    __shared__ float sy[64];
    sy[d] = y; __syncthreads();
    if (d < 16) {
        float p = (float)pos[t];
        float inv = powf(10000.0f, -(float)d / 16.0f);
        float ang = p * inv;
        float c = cosf(ang), s = sinf(ang);
        float x1 = sy[d], x2 = sy[d+16];
        base[d]    = x1*c - x2*s;
        base[d+16] = x1*s + x2*c;
    } else if (d >= 32) {
        base[d] = y;
    }
}

// ======== Flash-style attention ========
// block = (q-tile of 64, head). 256 threads (tx 0..15 -> keys/dims, ty 0..15 -> queries).
// K-tile = 32 keys. Online softmax, O accumulated in registers (4 queries x 4 dims / thread).
__global__ void __launch_bounds__(256) fattn_kernel() {
    __shared__ float Qs[64][68];   // [q][d]
    __shared__ float Ks[32][68];   // [k][d]
    __shared__ float Vs[32][68];   // [k][d]
    __shared__ float Ps[64][36];   // [q][k]
    int h = blockIdx.y;
    int kh = h >> 2;
    int q0 = blockIdx.x * 64;
    int tid = threadIdx.x;
    int tx = tid & 15, ty = tid >> 4;

    // load Q tile
    #pragma unroll
    for (int i = 0; i < 4; i++) {
        int idx = tid + i*256;             // 0..1023
        int q = idx >> 4, d = (idx & 15) << 2;
        *(float4*)&Qs[q][d] = *(const float4*)&g_qkv[(size_t)(q0+q)*QKV_N + h*HD + d];
    }

    float m_i[4], l_i[4], o[4][4];
    #pragma unroll
    for (int i = 0; i < 4; i++) {
        m_i[i] = -1e30f; l_i[i] = 0.f;
        #pragma unroll
        for (int j = 0; j < 4; j++) o[i][j] = 0.f;
    }

    int nkt = 2*blockIdx.x + 2;            // key tiles of 32 covering keys <= q0+63
    for (int kt = 0; kt < nkt; kt++) {
        int k0 = kt*32;
        // load K,V tiles (32x64 each)
        #pragma unroll
        for (int i = 0; i < 2; i++) {
            int idx = tid + i*256;         // 0..511
            int r = idx >> 4, d = (idx & 15) << 2;
            *(float4*)&Ks[r][d] = *(const float4*)&g_qkv[(size_t)(k0+r)*QKV_N + K_OFF + kh*HD + d];
            *(float4*)&Vs[r][d] = *(const float4*)&g_qkv[(size_t)(k0+r)*QKV_N + V_OFF + kh*HD + d];
        }
        __syncthreads();

        // scores: s[i][j], queries ty*4+i, keys tx*2+j
        float s[4][2] = {};
        #pragma unroll
        for (int d4 = 0; d4 < 64; d4 += 4) {
            float4 qv[4], kv[2];
            #pragma unroll
            for (int i = 0; i < 4; i++) qv[i] = *(float4*)&Qs[ty*4+i][d4];
            #pragma unroll
            for (int j = 0; j < 2; j++) kv[j] = *(float4*)&Ks[tx*2+j][d4];
            #pragma unroll
            for (int i = 0; i < 4; i++)
                #pragma unroll
                for (int j = 0; j < 2; j++)
                    s[i][j] += qv[i].x*kv[j].x + qv[i].y*kv[j].y + qv[i].z*kv[j].z + qv[i].w*kv[j].w;
        }
        // scale + causal mask
        #pragma unroll
        for (int i = 0; i < 4; i++) {
            int qg = q0 + ty*4 + i;
            #pragma unroll
            for (int j = 0; j < 2; j++) {
                int kg = k0 + tx*2 + j;
                s[i][j] = (kg <= qg) ? s[i][j]*0.125f : -1e30f;
            }
        }
        // row max across j and tx-group (16 lanes)
        #pragma unroll
        for (int i = 0; i < 4; i++) {
            float mt = fmaxf(s[i][0], s[i][1]);
            mt = fmaxf(mt, __shfl_xor_sync(0xffffffffu, mt, 1));
            mt = fmaxf(mt, __shfl_xor_sync(0xffffffffu, mt, 2));
            mt = fmaxf(mt, __shfl_xor_sync(0xffffffffu, mt, 4));
            mt = fmaxf(mt, __shfl_xor_sync(0xffffffffu, mt, 8));
            float mn = fmaxf(m_i[i], mt);
            float sc = __expf(m_i[i] - mn);
            float p0 = __expf(s[i][0] - mn);
            float p1 = __expf(s[i][1] - mn);
            float rs = p0 + p1;
            rs += __shfl_xor_sync(0xffffffffu, rs, 1);
            rs += __shfl_xor_sync(0xffffffffu, rs, 2);
            rs += __shfl_xor_sync(0xffffffffu, rs, 4);
            rs += __shfl_xor_sync(0xffffffffu, rs, 8);
            l_i[i] = l_i[i]*sc + rs;
            m_i[i] = mn;
            #pragma unroll
            for (int j = 0; j < 4; j++) o[i][j] *= sc;
            Ps[ty*4+i][tx*2+0] = p0;
            Ps[ty*4+i][tx*2+1] = p1;
        }
        __syncthreads();

        // O += P @ V  (dims tx*4..tx*4+3)
        #pragma unroll
        for (int s4 = 0; s4 < 32; s4 += 4) {
            float4 pv[4], vv[4];
            #pragma unroll
            for (int i = 0; i < 4; i++) pv[i] = *(float4*)&Ps[ty*4+i][s4];
            #pragma unroll
            for (int c = 0; c < 4; c++) vv[c] = *(float4*)&Vs[s4+c][tx*4];
            #pragma unroll
            for (int i = 0; i < 4; i++) {
                o[i][0] += pv[i].x*vv[0].x + pv[i].y*vv[1].x + pv[i].z*vv[2].x + pv[i].w*vv[3].x;
                o[i][1] += pv[i].x*vv[0].y + pv[i].y*vv[1].y + pv[i].z*vv[2].y + pv[i].w*vv[3].y;
                o[i][2] += pv[i].x*vv[0].z + pv[i].y*vv[1].z + pv[i].z*vv[2].z + pv[i].w*vv[3].z;
                o[i][3] += pv[i].x*vv[0].w + pv[i].y*vv[1].w + pv[i].z*vv[2].w + pv[i].w*vv[3].w;
            }
        }
        __syncthreads();
    }
    // epilogue
    #pragma unroll
    for (int i = 0; i < 4; i++) {
        float inv = 1.0f / l_i[i];
        int qg = q0 + ty*4 + i;
        *(float4*)&g_attno[(size_t)qg*H + h*HD + tx*4] =
            make_float4(o[i][0]*inv, o[i][1]*inv, o[i][2]*inv, o[i][3]*inv);
    }
}

// ---------------- router ----------------
__global__ void router_kernel(const float* __restrict__ Wg,
                              const float* __restrict__ gbias) {
    int t = blockIdx.x, tid = threadIdx.x;  // 32 threads
    __shared__ float sh[H];
    #pragma unroll
    for (int i = 0; i < H/32; i++) sh[tid + 32*i] = g_hidden3[(size_t)t*H + tid + 32*i];
    __syncthreads();
    float acc = 0.f;
    for (int k = 0; k < H; k++) acc += sh[k] * Wg[k*NE + tid];
    float scr = 1.0f / (1.0f + expf(-acc));
    float sfc = scr + gbias[tid];
    __shared__ float s_scr[NE], s_sfc[NE];
    s_scr[tid] = scr; s_sfc[tid] = sfc;
    __syncthreads();
    if (tid == 0) {
        float gs[NG];
        for (int g = 0; g < NG; g++) {
            float m1 = -1e30f, m2 = -1e30f;
            for (int j = 0; j < NE/NG; j++) {
                float v = s_sfc[g*(NE/NG) + j];
                if (v > m1) { m2 = m1; m1 = v; } else if (v > m2) m2 = v;
            }
            gs[g] = m1 + m2;
        }
        int g1 = 0; for (int g = 1; g < NG; g++) if (gs[g] > gs[g1]) g1 = g;
        int g2 = -1; for (int g = 0; g < NG; g++) { if (g == g1) continue; if (g2 < 0 || gs[g] > gs[g2]) g2 = g; }
        bool taken[NE];
        for (int e = 0; e < NE; e++) taken[e] = false;
        int ids[TOPK]; float wsum = 0.f;
        for (int j = 0; j < TOPK; j++) {
            int best = -1;
            for (int e = 0; e < NE; e++) {
                int g = e >> 3;
                if (g != g1 && g != g2) continue;
                if (taken[e]) continue;
                if (best < 0 || s_sfc[e] > s_sfc[best]) best = e;
            }
            taken[best] = true; ids[j] = best; wsum += s_scr[best];
        }
        for (int j = 0; j < TOPK; j++) {
            g_ids[t*TOPK + j] = ids[j];
            g_wts[t*TOPK + j] = s_scr[ids[j]] / wsum;
            atomicAdd(&g_cnt[ids[j]], 1);
        }
    }
}

__global__ void reset_kernel() { if (threadIdx.x < NE) g_cnt[threadIdx.x] = 0; }

__global__ void scan_kernel() {
    int tid = threadIdx.x;
    if (tid < NE) g_fill[tid] = 0;
    if (tid == 0) {
        int a = 0;
        for (int e = 0; e < NE; e++) { g_off[e] = a; a += g_cnt[e]; }
    }
}

__global__ void place_kernel() {
    int idx = blockIdx.x*blockDim.x + threadIdx.x;
    if (idx >= NPAIRS) return;
    int e = g_ids[idx];
    int p = g_off[e] + atomicAdd(&g_fill[e], 1);
    g_tok[p] = idx >> 2;
    g_pos[idx] = p;
}

// ======== MoE up GEMM: gathered rows, 128x128x16 tile ========
__global__ void __launch_bounds__(256) gemm_moe_up(const float* __restrict__ Wgu) {
    int e = blockIdx.z;
    int Me = g_cnt[e];
    int m0 = blockIdx.x * 128;
    if (m0 >= Me) return;
    int off = g_off[e];
    int n0 = blockIdx.y * 128;
    const float* Bp = Wgu + (size_t)e * H * (2*IM);
    __shared__ float As[16][132];
    __shared__ float Bs[16][128];
    __shared__ int srow[128];
    int tid = threadIdx.x;
    if (tid < 128) { int r = m0 + tid; srow[tid] = (r < Me) ? g_tok[off + r] : -1; }
    __syncthreads();
    int tx = tid & 15, ty = tid >> 4;
    float acc[8][8] = {};
    for (int k0 = 0; k0 < H; k0 += 16) {
        #pragma unroll
        for (int i = 0; i < 2; i++) {
            int idx = tid + i*256;
            int m = idx >> 2, kq = (idx & 3) << 2;
            int row = srow[m];
            float4 v = (row >= 0) ? *(const float4*)&g_hidden3[(size_t)row*H + k0 + kq]
                                  : make_float4(0.f,0.f,0.f,0.f);
            As[kq+0][m] = v.x; As[kq+1][m] = v.y; As[kq+2][m] = v.z; As[kq+3][m] = v.w;
        }
        #pragma unroll
        for (int i = 0; i < 2; i++) {
            int idx = tid + i*256;
            int k = idx >> 5, n = (idx & 31) << 2;
            *(float4*)&Bs[k][n] = *(const float4*)&Bp[(size_t)(k0+k)*(2*IM) + n0 + n];
        }
        __syncthreads();
        #pragma unroll
        for (int k = 0; k < 16; k++) {
            float a[8], b[8];
            *(float4*)&a[0] = *(float4*)&As[k][ty*8];
            *(float4*)&a[4] = *(float4*)&As[k][ty*8+4];
            *(float4*)&b[0] = *(float4*)&Bs[k][tx*8];
            *(float4*)&b[4] = *(float4*)&Bs[k][tx*8+4];
            #pragma unroll
            for (int i = 0; i < 8; i++)
                #pragma unroll
                for (int j = 0; j < 8; j++) acc[i][j] += a[i]*b[j];
        }
        __syncthreads();
    }
    #pragma unroll
    for (int i = 0; i < 8; i++) {
        int r = m0 + ty*8 + i;
        if (r < Me) {
            float* cp = &g_gu[(size_t)(off+r)*(2*IM) + n0 + tx*8];
            *(float4*)&cp[0] = make_float4(acc[i][0], acc[i][1], acc[i][2], acc[i][3]);
            *(float4*)&cp[4] = make_float4(acc[i][4], acc[i][5], acc[i][6], acc[i][7]);
        }
    }
}

// ======== MoE down GEMM: contiguous rows per expert ========
__global__ void __launch_bounds__(256) gemm_moe_down(const float* __restrict__ Wd) {
    int e = blockIdx.z;
    int Me = g_cnt[e];
    int m0 = blockIdx.x * 128;
    if (m0 >= Me) return;
    int off = g_off[e];
    int n0 = blockIdx.y * 128;
    const float* Ap = g_act + (size_t)off * IM;
    const float* Bp = Wd + (size_t)e * IM * H;
    __shared__ float As[16][132];
    __shared__ float Bs[16][128];
    int tid = threadIdx.x;
    int tx = tid & 15, ty = tid >> 4;
    float acc[8][8] = {};
    for (int k0 = 0; k0 < IM; k0 += 16) {
        #pragma unroll
        for (int i = 0; i < 2; i++) {
            int idx = tid + i*256;
            int m = idx >> 2, kq = (idx & 3) << 2;
            float4 v = (m0 + m < Me) ? *(const float4*)&Ap[(size_t)(m0+m)*IM + k0 + kq]
                                     : make_float4(0.f,0.f,0.f,0.f);
            As[kq+0][m] = v.x; As[kq+1][m] = v.y; As[kq+2][m] = v.z; As[kq+3][m] = v.w;
        }
        #pragma unroll
        for (int i = 0; i < 2; i++) {
            int idx = tid + i*256;
            int k = idx >> 5, n = (idx & 31) << 2;
            *(float4*)&Bs[k][n] = *(const float4*)&Bp[(size_t)(k0+k)*H + n0 + n];
        }
        __syncthreads();
        #pragma unroll
        for (int k = 0; k < 16; k++) {
            float a[8], b[8];
            *(float4*)&a[0] = *(float4*)&As[k][ty*8];
            *(float4*)&a[4] = *(float4*)&As[k][ty*8+4];
            *(float4*)&b[0] = *(float4*)&Bs[k][tx*8];
            *(float4*)&b[4] = *(float4*)&Bs[k][tx*8+4];
            #pragma unroll
            for (int i = 0; i < 8; i++)
                #pragma unroll
                for (int j = 0; j < 8; j++) acc[i][j] += a[i]*b[j];
        }
        __syncthreads();
    }
    #pragma unroll
    for (int i = 0; i < 8; i++) {
        int r = m0 + ty*8 + i;
        if (r < Me) {
            float* cp = &g_down[(size_t)(off+r)*H + n0 + tx*8];
            *(float4*)&cp[0] = make_float4(acc[i][0], acc[i][1], acc[i][2], acc[i][3]);
            *(float4*)&cp[4] = make_float4(acc[i][4], acc[i][5], acc[i][6], acc[i][7]);
        }
    }
}

// ---------------- SwiGLU activation ----------------
__global__ void act_kernel(int mode) {
    int idx = blockIdx.x*blockDim.x + threadIdx.x;
    if (mode == 0) {
        if (idx >= NPAIRS*IM) return;
        int r = idx / IM, j = idx % IM;
        float a = g_gu[(size_t)r*2*IM + j];
        float b = g_gu[(size_t)r*2*IM + IM + j];
        g_act[idx] = a / (1.0f + expf(-a)) * b;
    } else {
        if (idx >= T*ISH) return;
        int r = idx / ISH, j = idx % ISH;
        float a = g_sgu[(size_t)r*2*ISH + j];
        float b = g_sgu[(size_t)r*2*ISH + ISH + j];
        g_sact[idx] = a / (1.0f + expf(-a)) * b;
    }
}

// ---------------- final combine ----------------
__global__ void combine_kernel(float* __restrict__ out, int write_resid) {
    int idx = blockIdx.x*blockDim.x + threadIdx.x;
    if (idx >= T*H) return;
    int t = idx >> 10;
    int hh = idx & 1023;
    float acc = 0.f;
    #pragma unroll
    for (int s = 0; s < TOPK; s++) {
        int p = g_pos[t*TOPK + s];
        acc += g_wts[t*TOPK + s] * g_down[(size_t)p*H + hh];
    }
    out[idx] = acc + g_sout[idx];  // RSF = 1.0
    if (write_resid) out[(size_t)T*H + idx] = g_resid2[idx];
}

// ---------------- launch ----------------
extern "C" void kernel_launch(void* const* d_in, const int* in_sizes, int n_in,
                              void* d_out, int out_size) {
    const float* hidden_states = (const float*)d_in[0];
    const float* residual      = (const float*)d_in[1];
    const float* in_ln_w       = (const float*)d_in[2];
    const float* post_ln_w     = (const float*)d_in[3];
    const float* q_norm_w      = (const float*)d_in[4];
    const float* k_norm_w      = (const float*)d_in[5];
    const float* Wqkv          = (const float*)d_in[6];
    const float* Wo            = (const float*)d_in[7];
    const float* Wg            = (const float*)d_in[8];
    const float* gate_bias     = (const float*)d_in[9];
    const float* Wgu           = (const float*)d_in[10];
    const float* Wd            = (const float*)d_in[11];
    const float* Wgu_sh        = (const float*)d_in[12];
    const float* Wd_sh         = (const float*)d_in[13];
    const int*   positions     = (const int*)d_in[14];
    float* out = (float*)d_out;

    reset_kernel<<<1, 32>>>();
    add_rms_kernel<<<T, 256>>>(hidden_states, residual, in_ln_w, 0);
    k_gemm_qkv<<<dim3(QKV_N/128, T/128), 256>>>(Wqkv);
    qk_norm_rope_kernel<<<dim3(T, NH + NKV), 64>>>(q_norm_w, k_norm_w, positions);
    fattn_kernel<<<dim3(T/64, NH), 256>>>();
    k_gemm_wo<<<dim3(H/128, T/128), 256>>>(Wo);
    add_rms_kernel<<<T, 256>>>(nullptr, nullptr, post_ln_w, 1);
    router_kernel<<<T, 32>>>(Wg, gate_bias);
    scan_kernel<<<1, 32>>>();
    place_kernel<<<(NPAIRS + 255)/256, 256>>>();
    gemm_moe_up<<<dim3(T/128, 2*IM/128, NE), 256>>>(Wgu);
    act_kernel<<<(NPAIRS*IM + 255)/256, 256>>>(0);
    gemm_moe_down<<<dim3(T/128, H/128, NE), 256>>>(Wd);
    k_gemm_sgu<<<dim3(2*ISH/128, T/128), 256>>>(Wgu_sh);
    act_kernel<<<(T*ISH + 255)/256, 256>>>(1);
    k_gemm_sdown<<<dim3(H/128, T/128), 256>>>(Wd_sh);
    combine_kernel<<<(T*H + 255)/256, 256>>>(out, (out_size >= 2*T*H) ? 1 : 0);
}